// round 14
// baseline (speedup 1.0000x reference)
#include <cuda_runtime.h>
#include <math.h>
#include <stdint.h>

#define T_TOKENS 2048
#define HID      1024
#define INTER    2048
#define NEXP     8
#define NPAIRS   (T_TOKENS * 2)

// ---------------- scratch -----------------------------------------------------
__device__ int   g_counts[NEXP];
__device__ int   g_pairs[NEXP * NPAIRS];
__device__ float g_w[NPAIRS];
__device__ float g_xt[(size_t)T_TOKENS * HID];    // 8 MB  x in tf32
__device__ float g_h0[(size_t)NPAIRS * INTER];    // 32 MB x@wi0 (fp32)
__device__ float g_h1[(size_t)NPAIRS * INTER];    // 32 MB x@wi1 (fp32)
__device__ float g_inter[(size_t)NPAIRS * INTER]; // 32 MB tf32-rounded swiglu

// ---------------- helpers -------------------------------------------------------
__device__ __forceinline__ float tf(float f) {
    uint32_t r;
    asm("cvt.rna.tf32.f32 %0, %1;" : "=r"(r) : "f"(f));
    return __uint_as_float(r);
}
__device__ __forceinline__ uint32_t smem_u32(const void* p) {
    uint32_t a;
    asm("{ .reg .u64 t; cvta.to.shared.u64 t, %1; cvt.u32.u64 %0, t; }" : "=r"(a) : "l"(p));
    return a;
}
__device__ __forceinline__ void mma8(float* d, const uint32_t* a, const uint32_t* b) {
    asm volatile(
        "mma.sync.aligned.m16n8k8.row.col.f32.tf32.tf32.f32 "
        "{%0,%1,%2,%3}, {%4,%5,%6,%7}, {%8,%9}, {%0,%1,%2,%3};"
        : "+f"(d[0]), "+f"(d[1]), "+f"(d[2]), "+f"(d[3])
        : "r"(a[0]), "r"(a[1]), "r"(a[2]), "r"(a[3]), "r"(b[0]), "r"(b[1]));
}
__device__ __forceinline__ void ldsm4(uint32_t* r, uint32_t addr) {
    asm volatile("ldmatrix.sync.aligned.m8n8.x4.shared.b16 {%0,%1,%2,%3}, [%4];"
        : "=r"(r[0]), "=r"(r[1]), "=r"(r[2]), "=r"(r[3]) : "r"(addr));
}
__device__ __forceinline__ void cpa_z(uint32_t dst, const void* src, uint32_t sz) {
    asm volatile("cp.async.cg.shared.global [%0], [%1], 16, %2;" :: "r"(dst), "l"(src), "r"(sz));
}
#define CP_COMMIT() asm volatile("cp.async.commit_group;" ::: "memory")
#define CP_WAIT0()  asm volatile("cp.async.wait_group 0;" ::: "memory")

// ---------------- routing / small kernels ----------------------------------------
__global__ void zero_counts_kernel() {
    if (threadIdx.x < NEXP) g_counts[threadIdx.x] = 0;
}

__global__ void route_kernel(const float* __restrict__ logits) {
    int t = blockIdx.x * blockDim.x + threadIdx.x;
    if (t >= T_TOKENS) return;
    float l[NEXP];
#pragma unroll
    for (int e = 0; e < NEXP; e++) l[e] = logits[t * NEXP + e];
    int i0 = 0; float v0 = l[0];
#pragma unroll
    for (int e = 1; e < NEXP; e++) if (l[e] > v0) { v0 = l[e]; i0 = e; }
    int i1 = -1; float v1 = -__FLT_MAX__;
#pragma unroll
    for (int e = 0; e < NEXP; e++) {
        if (e == i0) continue;
        if (l[e] > v1) { v1 = l[e]; i1 = e; }
    }
    float e1 = expf(v1 - v0);
    float s  = 1.0f + e1;
    g_w[t * 2 + 0] = 1.0f / s;
    g_w[t * 2 + 1] = e1 / s;
    int p0 = atomicAdd(&g_counts[i0], 1);
    g_pairs[i0 * NPAIRS + p0] = t * 2 + 0;
    int p1 = atomicAdd(&g_counts[i1], 1);
    g_pairs[i1 * NPAIRS + p1] = t * 2 + 1;
}

__global__ void zero_out_kernel(float* __restrict__ out) {
    int i = blockIdx.x * blockDim.x + threadIdx.x;
    ((float4*)out)[i] = make_float4(0.f, 0.f, 0.f, 0.f);
}

__global__ void convert_x_kernel(const float* __restrict__ x) {
    int i = blockIdx.x * blockDim.x + threadIdx.x;
    float4 v = ((const float4*)x)[i];
    ((float4*)g_xt)[i] = make_float4(tf(v.x), tf(v.y), tf(v.z), tf(v.w));
}

// swiglu: g_inter = tf(silu(h0) * h1), elementwise (fp32 in, tf32-rounded out)
__global__ void swiglu_kernel() {
    int i = blockIdx.x * blockDim.x + threadIdx.x;
    float4 a = ((const float4*)g_h0)[i];
    float4 b = ((const float4*)g_h1)[i];
    float4 o;
    o.x = tf(a.x / (1.0f + __expf(-a.x)) * b.x);
    o.y = tf(a.y / (1.0f + __expf(-a.y)) * b.y);
    o.z = tf(a.z / (1.0f + __expf(-a.z)) * b.z);
    o.w = tf(a.w / (1.0f + __expf(-a.w)) * b.w);
    ((float4*)g_inter)[i] = o;
}

// ---------------- gemm_h: h = x @ wi[e]  (gemm2-clone structure) ------------------
// CTA 128M x 256N; warp tile 64x64; k-chunk 64 = 2 subtiles; double buffer.
// A via cp.async from tf32 g_xt; B reg-staged transpose. Plain fp32 store.
__global__ __launch_bounds__(256, 1) void gemm_h_mma(const float* __restrict__ wi,
                                                     float* __restrict__ hout)
{
    const int e   = blockIdx.z;
    const int cnt = g_counts[e];
    const int m0  = blockIdx.y * 128;
    if (m0 >= cnt) return;
    const int n0  = blockIdx.x * 256;
    const float* Bg = wi + (size_t)e * HID * INTER;

    extern __shared__ float smf[];
    unsigned char* smc = (unsigned char*)smf;   // A 2x32K @0; B 2x64K @64K
    const uint32_t sb = smem_u32(smc);

    const int tid = threadIdx.x, lane = tid & 31, wid = tid >> 5;
    const int wm = wid >> 2, wn = wid & 3;
    const int gq = lane >> 2, tg = lane & 3;
    const int l7 = lane & 7;

    const uint32_t aLane = (uint32_t)(wm * 64 + l7 + ((lane >> 3) & 1) * 8) * 128u;
    const int      c4a   = lane >> 4;
    const uint32_t bLane = (uint32_t)(wn * 64 + ((lane >> 4) & 1) * 8 + l7) * 128u;
    const int      c4b   = (lane >> 3) & 1;

    const int row = tid >> 1, half = tid & 1;
    const float* arow;
    uint32_t asz;
    {
        int mg = m0 + row;
        if (mg < cnt) { arow = g_xt + (size_t)(g_pairs[e * NPAIRS + mg] >> 1) * HID; asz = 16u; }
        else          { arow = g_xt; asz = 0u; }
    }
    auto cpA = [&](int buf, int k0, int sub) {
        const uint32_t st = sb + (uint32_t)buf * 32768u + (uint32_t)sub * 16384u;
#pragma unroll
        for (int q = 0; q < 4; q++) {
            int cchunk = half * 4 + q;
            uint32_t doff = (uint32_t)row * 128u + (uint32_t)((cchunk ^ (row & 7)) << 4);
            cpa_z(st + doff, arow + k0 + cchunk * 4, asz);
        }
    };

    const int bn = tid;   // 0..255
    float bR[32];
    auto loadB = [&](int k0) {
#pragma unroll
        for (int kk = 0; kk < 32; kk++)
            bR[kk] = Bg[(size_t)(k0 + kk) * INTER + n0 + bn];
    };
    auto storeB = [&](int buf, int sub) {
        unsigned char* b = smc + 65536 + buf * 65536 + sub * 32768;
#pragma unroll
        for (int g = 0; g < 8; g++) {
            uint32_t byte = (uint32_t)bn * 128u + (uint32_t)((g ^ (bn & 7)) << 4);
            *(float4*)(b + byte) = make_float4(tf(bR[g*4]), tf(bR[g*4+1]), tf(bR[g*4+2]), tf(bR[g*4+3]));
        }
    };

    float acc[4][8][4] = {};

    auto compute = [&](int buf, int sub) {
        const uint32_t ab = sb + buf * 32768 + sub * 16384 + aLane;
        const uint32_t bb = sb + 65536 + buf * 65536 + sub * 32768 + bLane;
#pragma unroll
        for (int ks = 0; ks < 4; ks++) {
            const int kc = ks * 2;
            const uint32_t ca = (uint32_t)(((kc + c4a) ^ l7) << 4);
            const uint32_t cb = (uint32_t)(((kc + c4b) ^ l7) << 4);
            uint32_t af[4][4];
#pragma unroll
            for (int i = 0; i < 4; i++) ldsm4(af[i], ab + i * 2048 + ca);
#pragma unroll
            for (int jp = 0; jp < 4; jp++) {
                uint32_t bf[4];
                ldsm4(bf, bb + jp * 2048 + cb);
#pragma unroll
                for (int i = 0; i < 4; i++) {
                    mma8(acc[i][jp * 2 + 0], af[i], bf + 0);
                    mma8(acc[i][jp * 2 + 1], af[i], bf + 2);
                }
            }
        }
    };

    // prologue
    cpA(0, 0, 0); cpA(0, 32, 1); CP_COMMIT();
    loadB(0);  storeB(0, 0);
    loadB(32); storeB(0, 1);
    CP_WAIT0();
    __syncthreads();

    const int C = HID / 64;   // 16 chunks
    for (int c = 0; c < C; c++) {
        const int buf = c & 1;
        const bool more = (c + 1 < C);
        const int nk = (c + 1) * 64;
        if (more) { cpA(buf ^ 1, nk, 0); cpA(buf ^ 1, nk + 32, 1); CP_COMMIT(); loadB(nk); }
        compute(buf, 0);
        if (more) { storeB(buf ^ 1, 0); loadB(nk + 32); }
        compute(buf, 1);
        if (more) storeB(buf ^ 1, 1);
        CP_WAIT0();
        __syncthreads();
    }

    // epilogue: plain fp32 store of h
#pragma unroll
    for (int i = 0; i < 4; i++) {
#pragma unroll
        for (int h = 0; h < 2; h++) {
            int m = m0 + wm * 64 + i * 16 + gq + h * 8;
            if (m >= cnt) continue;
            int entry = g_pairs[e * NPAIRS + m];
            float* orow = hout + (size_t)entry * INTER + n0 + wn * 64 + tg * 2;
#pragma unroll
            for (int j = 0; j < 8; j++)
                *(float2*)(orow + j * 8) = make_float2(acc[i][j][h * 2 + 0], acc[i][j][h * 2 + 1]);
        }
    }
}

// ---------------- GEMM2: inter @ wo[e], fused weighted combine -------------------
// UNCHANGED round-13 winner. CTA 128M x 256N; warp 64x64; k-chunk 64.
__global__ __launch_bounds__(256, 1) void gemm2_mma(const float* __restrict__ wo,
                                                    float* __restrict__ out)
{
    const int e   = blockIdx.z;
    const int cnt = g_counts[e];
    const int m0  = blockIdx.y * 128;
    if (m0 >= cnt) return;
    const int n0  = blockIdx.x * 256;
    const float* Bg = wo + (size_t)e * INTER * HID;

    extern __shared__ float smf[];
    unsigned char* smc = (unsigned char*)smf;
    const uint32_t sb = smem_u32(smc);

    const int tid = threadIdx.x, lane = tid & 31, wid = tid >> 5;
    const int wm = wid >> 2, wn = wid & 3;
    const int gq = lane >> 2, tg = lane & 3;
    const int l7 = lane & 7;

    const uint32_t aLane = (uint32_t)(wm * 64 + l7 + ((lane >> 3) & 1) * 8) * 128u;
    const int      c4a   = lane >> 4;
    const uint32_t bLane = (uint32_t)(wn * 64 + ((lane >> 4) & 1) * 8 + l7) * 128u;
    const int      c4b   = (lane >> 3) & 1;

    const int row = tid >> 1, half = tid & 1;
    const float* arow;
    uint32_t asz;
    {
        int mg = m0 + row;
        if (mg < cnt) { arow = g_inter + (size_t)g_pairs[e * NPAIRS + mg] * INTER; asz = 16u; }
        else          { arow = g_inter; asz = 0u; }
    }
    auto cpA = [&](int buf, int k0, int sub) {
        const uint32_t st = sb + (uint32_t)buf * 32768u + (uint32_t)sub * 16384u;
#pragma unroll
        for (int q = 0; q < 4; q++) {
            int cchunk = half * 4 + q;
            uint32_t doff = (uint32_t)row * 128u + (uint32_t)((cchunk ^ (row & 7)) << 4);
            cpa_z(st + doff, arow + k0 + cchunk * 4, asz);
        }
    };

    const int bn = tid;
    float bR[32];
    auto loadB = [&](int k0) {
#pragma unroll
        for (int kk = 0; kk < 32; kk++)
            bR[kk] = Bg[(size_t)(k0 + kk) * HID + n0 + bn];
    };
    auto storeB = [&](int buf, int sub) {
        unsigned char* b = smc + 65536 + buf * 65536 + sub * 32768;
#pragma unroll
        for (int g = 0; g < 8; g++) {
            uint32_t byte = (uint32_t)bn * 128u + (uint32_t)((g ^ (bn & 7)) << 4);
            *(float4*)(b + byte) = make_float4(tf(bR[g*4]), tf(bR[g*4+1]), tf(bR[g*4+2]), tf(bR[g*4+3]));
        }
    };

    float acc[4][8][4] = {};

    auto compute = [&](int buf, int sub) {
        const uint32_t ab = sb + buf * 32768 + sub * 16384 + aLane;
        const uint32_t bb = sb + 65536 + buf * 65536 + sub * 32768 + bLane;
#pragma unroll
        for (int ks = 0; ks < 4; ks++) {
            const int kc = ks * 2;
            const uint32_t ca = (uint32_t)(((kc + c4a) ^ l7) << 4);
            const uint32_t cb = (uint32_t)(((kc + c4b) ^ l7) << 4);
            uint32_t af[4][4];
#pragma unroll
            for (int i = 0; i < 4; i++) ldsm4(af[i], ab + i * 2048 + ca);
#pragma unroll
            for (int jp = 0; jp < 4; jp++) {
                uint32_t bf[4];
                ldsm4(bf, bb + jp * 2048 + cb);
#pragma unroll
                for (int i = 0; i < 4; i++) {
                    mma8(acc[i][jp * 2 + 0], af[i], bf + 0);
                    mma8(acc[i][jp * 2 + 1], af[i], bf + 2);
                }
            }
        }
    };

    cpA(0, 0, 0); cpA(0, 32, 1); CP_COMMIT();
    loadB(0);  storeB(0, 0);
    loadB(32); storeB(0, 1);
    CP_WAIT0();
    __syncthreads();

    const int C = INTER / 64;
    for (int c = 0; c < C; c++) {
        const int buf = c & 1;
        const bool more = (c + 1 < C);
        const int nk = (c + 1) * 64;
        if (more) { cpA(buf ^ 1, nk, 0); cpA(buf ^ 1, nk + 32, 1); CP_COMMIT(); loadB(nk); }
        compute(buf, 0);
        if (more) { storeB(buf ^ 1, 0); loadB(nk + 32); }
        compute(buf, 1);
        if (more) storeB(buf ^ 1, 1);
        CP_WAIT0();
        __syncthreads();
    }

#pragma unroll
    for (int i = 0; i < 4; i++) {
#pragma unroll
        for (int h = 0; h < 2; h++) {
            int m = m0 + wm * 64 + i * 16 + gq + h * 8;
            if (m >= cnt) continue;
            int entry = g_pairs[e * NPAIRS + m];
            float w = g_w[entry];
            float* base = out + (size_t)(entry >> 1) * HID + n0 + wn * 64 + tg * 2;
#pragma unroll
            for (int j = 0; j < 8; j++) {
                atomicAdd(base + j * 8 + 0, w * acc[i][j][h * 2 + 0]);
                atomicAdd(base + j * 8 + 1, w * acc[i][j][h * 2 + 1]);
            }
        }
    }
}

// ---------------- launch -------------------------------------------------------------
extern "C" void kernel_launch(void* const* d_in, const int* in_sizes, int n_in,
                              void* d_out, int out_size)
{
    const float* x      = (const float*)d_in[0];
    const float* logits = (const float*)d_in[1];
    const float* wi0    = (const float*)d_in[2];
    const float* wi1    = (const float*)d_in[3];
    const float* wo     = (const float*)d_in[4];
    float* out          = (float*)d_out;

    const int g_smem = 196608;   // 192 KB
    cudaFuncSetAttribute(gemm_h_mma, cudaFuncAttributeMaxDynamicSharedMemorySize, g_smem);
    cudaFuncSetAttribute(gemm2_mma,  cudaFuncAttributeMaxDynamicSharedMemorySize, g_smem);

    float* h0; cudaGetSymbolAddress((void**)&h0, g_h0);
    float* h1; cudaGetSymbolAddress((void**)&h1, g_h1);

    zero_counts_kernel<<<1, 32>>>();
    route_kernel<<<T_TOKENS / 256, 256>>>(logits);
    zero_out_kernel<<<(T_TOKENS * HID / 4) / 256, 256>>>(out);
    convert_x_kernel<<<(T_TOKENS * HID / 4) / 256, 256>>>(x);

    dim3 g1(INTER / 256, NPAIRS / 128, NEXP);   // (8, 32, 8)
    gemm_h_mma<<<g1, 256, g_smem>>>(wi0, h0);
    gemm_h_mma<<<g1, 256, g_smem>>>(wi1, h1);

    swiglu_kernel<<<((size_t)NPAIRS * INTER / 4) / 256, 256>>>();

    dim3 g2(HID / 256, NPAIRS / 128, NEXP);     // (4, 32, 8)
    gemm2_mma<<<g2, 256, g_smem>>>(wo, out);
}

// round 16
// speedup vs baseline: 1.0127x; 1.0127x over previous
#include <cuda_runtime.h>
#include <math.h>
#include <stdint.h>

#define T_TOKENS 2048
#define HID      1024
#define INTER    2048
#define NEXP     8
#define NPAIRS   (T_TOKENS * 2)

// ---------------- scratch -----------------------------------------------------
__device__ int   g_counts[NEXP];
__device__ int   g_pairs[NEXP * NPAIRS];
__device__ float g_w[NPAIRS];
__device__ float g_inter[(size_t)NPAIRS * INTER]; // 32 MB (tf32-rounded)

// ---------------- helpers -------------------------------------------------------
__device__ __forceinline__ float tf(float f) {
    uint32_t r;
    asm("cvt.rna.tf32.f32 %0, %1;" : "=r"(r) : "f"(f));
    return __uint_as_float(r);
}
__device__ __forceinline__ uint32_t smem_u32(const void* p) {
    uint32_t a;
    asm("{ .reg .u64 t; cvta.to.shared.u64 t, %1; cvt.u32.u64 %0, t; }" : "=r"(a) : "l"(p));
    return a;
}
__device__ __forceinline__ void mma8(float* d, const uint32_t* a, const uint32_t* b) {
    asm volatile(
        "mma.sync.aligned.m16n8k8.row.col.f32.tf32.tf32.f32 "
        "{%0,%1,%2,%3}, {%4,%5,%6,%7}, {%8,%9}, {%0,%1,%2,%3};"
        : "+f"(d[0]), "+f"(d[1]), "+f"(d[2]), "+f"(d[3])
        : "r"(a[0]), "r"(a[1]), "r"(a[2]), "r"(a[3]), "r"(b[0]), "r"(b[1]));
}
__device__ __forceinline__ void ldsm4(uint32_t* r, uint32_t addr) {
    asm volatile("ldmatrix.sync.aligned.m8n8.x4.shared.b16 {%0,%1,%2,%3}, [%4];"
        : "=r"(r[0]), "=r"(r[1]), "=r"(r[2]), "=r"(r[3]) : "r"(addr));
}
__device__ __forceinline__ void cpa_z(uint32_t dst, const void* src, uint32_t sz) {
    asm volatile("cp.async.cg.shared.global [%0], [%1], 16, %2;" :: "r"(dst), "l"(src), "r"(sz));
}
#define CP_COMMIT() asm volatile("cp.async.commit_group;" ::: "memory")
#define CP_WAIT0()  asm volatile("cp.async.wait_group 0;" ::: "memory")

// ---------------- routing / small kernels ----------------------------------------
__global__ void zero_counts_kernel() {
    if (threadIdx.x < NEXP) g_counts[threadIdx.x] = 0;
}

__global__ void route_kernel(const float* __restrict__ logits) {
    int t = blockIdx.x * blockDim.x + threadIdx.x;
    if (t >= T_TOKENS) return;
    float l[NEXP];
#pragma unroll
    for (int e = 0; e < NEXP; e++) l[e] = logits[t * NEXP + e];
    int i0 = 0; float v0 = l[0];
#pragma unroll
    for (int e = 1; e < NEXP; e++) if (l[e] > v0) { v0 = l[e]; i0 = e; }
    int i1 = -1; float v1 = -__FLT_MAX__;
#pragma unroll
    for (int e = 0; e < NEXP; e++) {
        if (e == i0) continue;
        if (l[e] > v1) { v1 = l[e]; i1 = e; }
    }
    float e1 = expf(v1 - v0);
    float s  = 1.0f + e1;
    g_w[t * 2 + 0] = 1.0f / s;
    g_w[t * 2 + 1] = e1 / s;
    int p0 = atomicAdd(&g_counts[i0], 1);
    g_pairs[i0 * NPAIRS + p0] = t * 2 + 0;
    int p1 = atomicAdd(&g_counts[i1], 1);
    g_pairs[i1 * NPAIRS + p1] = t * 2 + 1;
}

__global__ void zero_out_kernel(float* __restrict__ out) {
    int i = blockIdx.x * blockDim.x + threadIdx.x;
    ((float4*)out)[i] = make_float4(0.f, 0.f, 0.f, 0.f);
}

// ---------------- GEMM1: x @ {wi0, wi1}[e] + fused SwiGLU ------------------------
// EXACT round-13 structure. CTA 128M x 128N (per matrix); k-chunk 64 = 2 subtiles.
__global__ __launch_bounds__(256, 1) void gemm1_mma(
    const float* __restrict__ x,
    const float* __restrict__ wi0,
    const float* __restrict__ wi1)
{
    const int e   = blockIdx.z;
    const int cnt = g_counts[e];
    const int m0  = blockIdx.y * 128;
    if (m0 >= cnt) return;
    const int n0  = blockIdx.x * 128;
    const float* B0g = wi0 + (size_t)e * HID * INTER;
    const float* B1g = wi1 + (size_t)e * HID * INTER;

    extern __shared__ float smf[];
    unsigned char* smc = (unsigned char*)smf;
    const uint32_t sb = smem_u32(smc);

    const int tid = threadIdx.x, lane = tid & 31, wid = tid >> 5;
    const int wm = wid >> 2, wn = wid & 3;
    const int gq = lane >> 2, tg = lane & 3;
    const int l7 = lane & 7;

    const uint32_t aLane = (uint32_t)(wm * 64 + l7 + ((lane >> 3) & 1) * 8) * 128u;
    const int      c4a   = lane >> 4;
    const uint32_t bLane = (uint32_t)(wn * 32 + ((lane >> 4) & 1) * 8 + l7) * 128u;
    const int      c4b   = (lane >> 3) & 1;

    const int ar = tid >> 1, side = tid & 1;
    const float* arow = nullptr;
    {
        int mg = m0 + ar;
        if (mg < cnt) arow = x + (size_t)(g_pairs[e * NPAIRS + mg] >> 1) * HID;
    }
    const int bn = tid & 127, bkg = (tid >> 7) * 16;

    float4 aR[4];
    float  b0R[16], b1R[16];

    auto loadA = [&](int k0) {
#pragma unroll
        for (int q = 0; q < 4; q++)
            aR[q] = arow ? *(const float4*)(arow + k0 + side * 16 + q * 4)
                         : make_float4(0.f, 0.f, 0.f, 0.f);
    };
    auto loadB = [&](int k0) {
#pragma unroll
        for (int kk = 0; kk < 16; kk++) {
            size_t off = (size_t)(k0 + bkg + kk) * INTER + n0 + bn;
            b0R[kk] = B0g[off];
            b1R[kk] = B1g[off];
        }
    };
    auto storeA = [&](int buf, int sub) {
        unsigned char* a = smc + buf * 32768 + sub * 16384;
#pragma unroll
        for (int q = 0; q < 4; q++) {
            uint32_t byte = (uint32_t)ar * 128u + (uint32_t)(((side * 4 + q) ^ (ar & 7)) << 4);
            *(float4*)(a + byte) = make_float4(tf(aR[q].x), tf(aR[q].y), tf(aR[q].z), tf(aR[q].w));
        }
    };
    auto storeB = [&](int buf, int sub) {
        unsigned char* b0 = smc + 65536  + buf * 32768 + sub * 16384;
        unsigned char* b1 = smc + 131072 + buf * 32768 + sub * 16384;
#pragma unroll
        for (int g = 0; g < 4; g++) {
            uint32_t byte = (uint32_t)bn * 128u + (uint32_t)((((bkg >> 2) + g) ^ (bn & 7)) << 4);
            *(float4*)(b0 + byte) = make_float4(tf(b0R[g*4]), tf(b0R[g*4+1]), tf(b0R[g*4+2]), tf(b0R[g*4+3]));
            *(float4*)(b1 + byte) = make_float4(tf(b1R[g*4]), tf(b1R[g*4+1]), tf(b1R[g*4+2]), tf(b1R[g*4+3]));
        }
    };

    float acc0[4][4][4] = {}, acc1[4][4][4] = {};

    auto compute = [&](int buf, int sub) {
        const uint32_t ab  = sb + buf * 32768 + sub * 16384 + aLane;
        const uint32_t b0b = sb + 65536  + buf * 32768 + sub * 16384 + bLane;
        const uint32_t b1b = sb + 131072 + buf * 32768 + sub * 16384 + bLane;
#pragma unroll
        for (int ks = 0; ks < 4; ks++) {
            const int kc = ks * 2;
            const uint32_t ca = (uint32_t)(((kc + c4a) ^ l7) << 4);
            const uint32_t cb = (uint32_t)(((kc + c4b) ^ l7) << 4);
            uint32_t af[4][4];
#pragma unroll
            for (int i = 0; i < 4; i++) ldsm4(af[i], ab + i * 2048 + ca);
#pragma unroll
            for (int jp = 0; jp < 2; jp++) {
                uint32_t f0[4], f1[4];
                ldsm4(f0, b0b + jp * 2048 + cb);
                ldsm4(f1, b1b + jp * 2048 + cb);
#pragma unroll
                for (int i = 0; i < 4; i++) {
                    mma8(acc0[i][jp * 2 + 0], af[i], f0 + 0);
                    mma8(acc0[i][jp * 2 + 1], af[i], f0 + 2);
                    mma8(acc1[i][jp * 2 + 0], af[i], f1 + 0);
                    mma8(acc1[i][jp * 2 + 1], af[i], f1 + 2);
                }
            }
        }
    };

    loadA(0);  loadB(0);  storeA(0, 0); storeB(0, 0);
    loadA(32); loadB(32); storeA(0, 1); storeB(0, 1);
    __syncthreads();

    const int C = HID / 64;
    for (int c = 0; c < C; c++) {
        const int buf = c & 1;
        const bool more = (c + 1 < C);
        const int nk = (c + 1) * 64;
        if (more) { loadA(nk); loadB(nk); }
        compute(buf, 0);
        if (more) { storeA(buf ^ 1, 0); storeB(buf ^ 1, 0); loadA(nk + 32); loadB(nk + 32); }
        compute(buf, 1);
        if (more) { storeA(buf ^ 1, 1); storeB(buf ^ 1, 1); }
        __syncthreads();
    }

#pragma unroll
    for (int i = 0; i < 4; i++) {
#pragma unroll
        for (int h = 0; h < 2; h++) {
            int m = m0 + wm * 64 + i * 16 + gq + h * 8;
            if (m >= cnt) continue;
            int entry = g_pairs[e * NPAIRS + m];
            float* orow = g_inter + (size_t)entry * INTER + n0 + wn * 32;
#pragma unroll
            for (int j = 0; j < 4; j++) {
                float h0a = acc0[i][j][h * 2 + 0], h0b = acc0[i][j][h * 2 + 1];
                float h1a = acc1[i][j][h * 2 + 0], h1b = acc1[i][j][h * 2 + 1];
                float oa = tf(h0a / (1.0f + __expf(-h0a)) * h1a);
                float ob = tf(h0b / (1.0f + __expf(-h0b)) * h1b);
                *(float2*)(orow + j * 8 + tg * 2) = make_float2(oa, ob);
            }
        }
    }
}

// ---------------- GEMM2: inter @ wo[e], fused weighted combine -------------------
// CTA 128M x 128N; warp tile 64x32 (acc 64 regs); k-chunk 32; 2 CTAs/SM.
// A via cp.async from tf32 g_inter; B reg-staged transpose. smem 64KB/CTA.
__global__ __launch_bounds__(256, 2) void gemm2_mma(const float* __restrict__ wo,
                                                    float* __restrict__ out)
{
    const int e   = blockIdx.z;
    const int cnt = g_counts[e];
    const int m0  = blockIdx.y * 128;
    if (m0 >= cnt) return;
    const int n0  = blockIdx.x * 128;
    const float* Bg = wo + (size_t)e * INTER * HID;

    extern __shared__ float smf[];
    unsigned char* smc = (unsigned char*)smf;   // A: 2x16K @0; B: 2x16K @32K
    const uint32_t sb = smem_u32(smc);

    const int tid = threadIdx.x, lane = tid & 31, wid = tid >> 5;
    const int wm = wid >> 2, wn = wid & 3;
    const int gq = lane >> 2, tg = lane & 3;
    const int l7 = lane & 7;

    const uint32_t aLane = (uint32_t)(wm * 64 + l7 + ((lane >> 3) & 1) * 8) * 128u;
    const int      c4a   = lane >> 4;
    const uint32_t bLane = (uint32_t)(wn * 32 + ((lane >> 4) & 1) * 8 + l7) * 128u;
    const int      c4b   = (lane >> 3) & 1;

    const int row = tid >> 1, half = tid & 1;
    const float* arow;
    uint32_t asz;
    {
        int mg = m0 + row;
        if (mg < cnt) { arow = g_inter + (size_t)g_pairs[e * NPAIRS + mg] * INTER; asz = 16u; }
        else          { arow = g_inter; asz = 0u; }
    }
    auto cpA = [&](int buf, int k0) {
        const uint32_t st = sb + (uint32_t)buf * 16384u;
#pragma unroll
        for (int q = 0; q < 4; q++) {
            int cchunk = half * 4 + q;
            uint32_t doff = (uint32_t)row * 128u + (uint32_t)((cchunk ^ (row & 7)) << 4);
            cpa_z(st + doff, arow + k0 + cchunk * 4, asz);
        }
    };

    const int bn = tid & 127, bkg = (tid >> 7) * 16;
    float bR[16];
    auto loadB = [&](int k0) {
#pragma unroll
        for (int kk = 0; kk < 16; kk++)
            bR[kk] = Bg[(size_t)(k0 + bkg + kk) * HID + n0 + bn];
    };
    auto storeB = [&](int buf) {
        unsigned char* b = smc + 32768 + buf * 16384;
#pragma unroll
        for (int g = 0; g < 4; g++) {
            uint32_t byte = (uint32_t)bn * 128u + (uint32_t)((((bkg >> 2) + g) ^ (bn & 7)) << 4);
            *(float4*)(b + byte) = make_float4(tf(bR[g*4]), tf(bR[g*4+1]), tf(bR[g*4+2]), tf(bR[g*4+3]));
        }
    };

    float acc[4][4][4] = {};

    auto compute = [&](int buf) {
        const uint32_t ab = sb + buf * 16384 + aLane;
        const uint32_t bb = sb + 32768 + buf * 16384 + bLane;
#pragma unroll
        for (int ks = 0; ks < 4; ks++) {
            const int kc = ks * 2;
            const uint32_t ca = (uint32_t)(((kc + c4a) ^ l7) << 4);
            const uint32_t cb = (uint32_t)(((kc + c4b) ^ l7) << 4);
            uint32_t af[4][4];
#pragma unroll
            for (int i = 0; i < 4; i++) ldsm4(af[i], ab + i * 2048 + ca);
            uint32_t bf[4], bf2[4];
            ldsm4(bf,  bb + cb);          // n-cols wn*32 .. wn*32+15
            ldsm4(bf2, bb + 2048 + cb);   // n-cols wn*32+16 .. wn*32+31
#pragma unroll
            for (int i = 0; i < 4; i++) {
                mma8(acc[i][0], af[i], bf  + 0);
                mma8(acc[i][1], af[i], bf  + 2);
                mma8(acc[i][2], af[i], bf2 + 0);
                mma8(acc[i][3], af[i], bf2 + 2);
            }
        }
    };

    // prologue
    cpA(0, 0); CP_COMMIT();
    loadB(0);
    CP_WAIT0();
    storeB(0);
    __syncthreads();

    const int C = INTER / 32;
    for (int c = 0; c < C; c++) {
        const int buf = c & 1;
        const bool more = (c + 1 < C);
        if (more) { cpA(buf ^ 1, (c + 1) * 32); CP_COMMIT(); loadB((c + 1) * 32); }
        compute(buf);
        if (more) storeB(buf ^ 1);
        CP_WAIT0();
        __syncthreads();
    }

    // fused combine: out[token] += w * y  (bitwise deterministic)
#pragma unroll
    for (int i = 0; i < 4; i++) {
#pragma unroll
        for (int h = 0; h < 2; h++) {
            int m = m0 + wm * 64 + i * 16 + gq + h * 8;
            if (m >= cnt) continue;
            int entry = g_pairs[e * NPAIRS + m];
            float w = g_w[entry];
            float* base = out + (size_t)(entry >> 1) * HID + n0 + wn * 32 + tg * 2;
#pragma unroll
            for (int j = 0; j < 4; j++) {
                atomicAdd(base + j * 8 + 0, w * acc[i][j][h * 2 + 0]);
                atomicAdd(base + j * 8 + 1, w * acc[i][j][h * 2 + 1]);
            }
        }
    }
}

// ---------------- launch -------------------------------------------------------------
extern "C" void kernel_launch(void* const* d_in, const int* in_sizes, int n_in,
                              void* d_out, int out_size)
{
    const float* x      = (const float*)d_in[0];
    const float* logits = (const float*)d_in[1];
    const float* wi0    = (const float*)d_in[2];
    const float* wi1    = (const float*)d_in[3];
    const float* wo     = (const float*)d_in[4];
    float* out          = (float*)d_out;

    const int g1_smem = 196608;  // 192 KB
    const int g2_smem = 65536;   // 64 KB x 2 CTAs/SM = 128 KB
    cudaFuncSetAttribute(gemm1_mma, cudaFuncAttributeMaxDynamicSharedMemorySize, g1_smem);
    cudaFuncSetAttribute(gemm2_mma, cudaFuncAttributeMaxDynamicSharedMemorySize, g2_smem);

    zero_counts_kernel<<<1, 32>>>();
    route_kernel<<<T_TOKENS / 256, 256>>>(logits);
    zero_out_kernel<<<(T_TOKENS * HID / 4) / 256, 256>>>(out);

    dim3 g1(INTER / 128, NPAIRS / 128, NEXP);   // (16, 32, 8)
    gemm1_mma<<<g1, 256, g1_smem>>>(x, wi0, wi1);

    dim3 g2(HID / 128, NPAIRS / 128, NEXP);     // (8, 32, 8)
    gemm2_mma<<<g2, 256, g2_smem>>>(wo, out);
}

// round 17
// speedup vs baseline: 1.0509x; 1.0377x over previous
#include <cuda_runtime.h>
#include <math.h>
#include <stdint.h>

#define T_TOKENS 2048
#define HID      1024
#define INTER    2048
#define NEXP     8
#define NPAIRS   (T_TOKENS * 2)

// ---------------- scratch -----------------------------------------------------
__device__ int   g_counts[NEXP];
__device__ int   g_pairs[NEXP * NPAIRS];
__device__ float g_w[NPAIRS];
__device__ float g_inter[(size_t)NPAIRS * INTER]; // 32 MB (tf32-rounded)

// ---------------- helpers -------------------------------------------------------
__device__ __forceinline__ float tf(float f) {
    uint32_t r;
    asm("cvt.rna.tf32.f32 %0, %1;" : "=r"(r) : "f"(f));
    return __uint_as_float(r);
}
__device__ __forceinline__ uint32_t smem_u32(const void* p) {
    uint32_t a;
    asm("{ .reg .u64 t; cvta.to.shared.u64 t, %1; cvt.u32.u64 %0, t; }" : "=r"(a) : "l"(p));
    return a;
}
__device__ __forceinline__ void mma8(float* d, const uint32_t* a, const uint32_t* b) {
    asm volatile(
        "mma.sync.aligned.m16n8k8.row.col.f32.tf32.tf32.f32 "
        "{%0,%1,%2,%3}, {%4,%5,%6,%7}, {%8,%9}, {%0,%1,%2,%3};"
        : "+f"(d[0]), "+f"(d[1]), "+f"(d[2]), "+f"(d[3])
        : "r"(a[0]), "r"(a[1]), "r"(a[2]), "r"(a[3]), "r"(b[0]), "r"(b[1]));
}
__device__ __forceinline__ void ldsm4(uint32_t* r, uint32_t addr) {
    asm volatile("ldmatrix.sync.aligned.m8n8.x4.shared.b16 {%0,%1,%2,%3}, [%4];"
        : "=r"(r[0]), "=r"(r[1]), "=r"(r[2]), "=r"(r[3]) : "r"(addr));
}
__device__ __forceinline__ void cpa_z(uint32_t dst, const void* src, uint32_t sz) {
    asm volatile("cp.async.cg.shared.global [%0], [%1], 16, %2;" :: "r"(dst), "l"(src), "r"(sz));
}
#define CP_COMMIT() asm volatile("cp.async.commit_group;" ::: "memory")
#define CP_WAIT0()  asm volatile("cp.async.wait_group 0;" ::: "memory")

// ---------------- routing / small kernels ----------------------------------------
// zero_out also zeroes the expert counters (block 0); route runs after in-stream.
__global__ void zero_out_kernel(float* __restrict__ out) {
    int i = blockIdx.x * blockDim.x + threadIdx.x;
    ((float4*)out)[i] = make_float4(0.f, 0.f, 0.f, 0.f);
    if (blockIdx.x == 0 && threadIdx.x < NEXP) g_counts[threadIdx.x] = 0;
}

__global__ void route_kernel(const float* __restrict__ logits) {
    int t = blockIdx.x * blockDim.x + threadIdx.x;
    if (t >= T_TOKENS) return;
    float l[NEXP];
#pragma unroll
    for (int e = 0; e < NEXP; e++) l[e] = logits[t * NEXP + e];
    int i0 = 0; float v0 = l[0];
#pragma unroll
    for (int e = 1; e < NEXP; e++) if (l[e] > v0) { v0 = l[e]; i0 = e; }
    int i1 = -1; float v1 = -__FLT_MAX__;
#pragma unroll
    for (int e = 0; e < NEXP; e++) {
        if (e == i0) continue;
        if (l[e] > v1) { v1 = l[e]; i1 = e; }
    }
    float e1 = expf(v1 - v0);
    float s  = 1.0f + e1;
    g_w[t * 2 + 0] = 1.0f / s;
    g_w[t * 2 + 1] = e1 / s;
    int p0 = atomicAdd(&g_counts[i0], 1);
    g_pairs[i0 * NPAIRS + p0] = t * 2 + 0;
    int p1 = atomicAdd(&g_counts[i1], 1);
    g_pairs[i1 * NPAIRS + p1] = t * 2 + 1;
}

// ---------------- GEMM1: x @ {wi0, wi1}[e] + fused SwiGLU ------------------------
// Round-13 structure (best known). CTA 128M x 128N (per matrix);
// k-chunk 64 = 2 x 32-k subtiles; double buffer; SW128 smem.
__global__ __launch_bounds__(256, 1) void gemm1_mma(
    const float* __restrict__ x,
    const float* __restrict__ wi0,
    const float* __restrict__ wi1)
{
    const int e   = blockIdx.z;
    const int cnt = g_counts[e];
    const int m0  = blockIdx.y * 128;
    if (m0 >= cnt) return;
    const int n0  = blockIdx.x * 128;
    const float* B0g = wi0 + (size_t)e * HID * INTER;
    const float* B1g = wi1 + (size_t)e * HID * INTER;

    extern __shared__ float smf[];
    unsigned char* smc = (unsigned char*)smf;
    const uint32_t sb = smem_u32(smc);

    const int tid = threadIdx.x, lane = tid & 31, wid = tid >> 5;
    const int wm = wid >> 2, wn = wid & 3;
    const int gq = lane >> 2, tg = lane & 3;
    const int l7 = lane & 7;

    const uint32_t aLane = (uint32_t)(wm * 64 + l7 + ((lane >> 3) & 1) * 8) * 128u;
    const int      c4a   = lane >> 4;
    const uint32_t bLane = (uint32_t)(wn * 32 + ((lane >> 4) & 1) * 8 + l7) * 128u;
    const int      c4b   = (lane >> 3) & 1;

    const int ar = tid >> 1, side = tid & 1;
    const float* arow = nullptr;
    {
        int mg = m0 + ar;
        if (mg < cnt) arow = x + (size_t)(g_pairs[e * NPAIRS + mg] >> 1) * HID;
    }
    const int bn = tid & 127, bkg = (tid >> 7) * 16;

    float4 aR[4];
    float  b0R[16], b1R[16];

    auto loadA = [&](int k0) {
#pragma unroll
        for (int q = 0; q < 4; q++)
            aR[q] = arow ? *(const float4*)(arow + k0 + side * 16 + q * 4)
                         : make_float4(0.f, 0.f, 0.f, 0.f);
    };
    auto loadB = [&](int k0) {
#pragma unroll
        for (int kk = 0; kk < 16; kk++) {
            size_t off = (size_t)(k0 + bkg + kk) * INTER + n0 + bn;
            b0R[kk] = B0g[off];
            b1R[kk] = B1g[off];
        }
    };
    auto storeA = [&](int buf, int sub) {
        unsigned char* a = smc + buf * 32768 + sub * 16384;
#pragma unroll
        for (int q = 0; q < 4; q++) {
            uint32_t byte = (uint32_t)ar * 128u + (uint32_t)(((side * 4 + q) ^ (ar & 7)) << 4);
            *(float4*)(a + byte) = make_float4(tf(aR[q].x), tf(aR[q].y), tf(aR[q].z), tf(aR[q].w));
        }
    };
    auto storeB = [&](int buf, int sub) {
        unsigned char* b0 = smc + 65536  + buf * 32768 + sub * 16384;
        unsigned char* b1 = smc + 131072 + buf * 32768 + sub * 16384;
#pragma unroll
        for (int g = 0; g < 4; g++) {
            uint32_t byte = (uint32_t)bn * 128u + (uint32_t)((((bkg >> 2) + g) ^ (bn & 7)) << 4);
            *(float4*)(b0 + byte) = make_float4(tf(b0R[g*4]), tf(b0R[g*4+1]), tf(b0R[g*4+2]), tf(b0R[g*4+3]));
            *(float4*)(b1 + byte) = make_float4(tf(b1R[g*4]), tf(b1R[g*4+1]), tf(b1R[g*4+2]), tf(b1R[g*4+3]));
        }
    };

    float acc0[4][4][4] = {}, acc1[4][4][4] = {};

    auto compute = [&](int buf, int sub) {
        const uint32_t ab  = sb + buf * 32768 + sub * 16384 + aLane;
        const uint32_t b0b = sb + 65536  + buf * 32768 + sub * 16384 + bLane;
        const uint32_t b1b = sb + 131072 + buf * 32768 + sub * 16384 + bLane;
#pragma unroll
        for (int ks = 0; ks < 4; ks++) {
            const int kc = ks * 2;
            const uint32_t ca = (uint32_t)(((kc + c4a) ^ l7) << 4);
            const uint32_t cb = (uint32_t)(((kc + c4b) ^ l7) << 4);
            uint32_t af[4][4];
#pragma unroll
            for (int i = 0; i < 4; i++) ldsm4(af[i], ab + i * 2048 + ca);
#pragma unroll
            for (int jp = 0; jp < 2; jp++) {
                uint32_t f0[4], f1[4];
                ldsm4(f0, b0b + jp * 2048 + cb);
                ldsm4(f1, b1b + jp * 2048 + cb);
#pragma unroll
                for (int i = 0; i < 4; i++) {
                    mma8(acc0[i][jp * 2 + 0], af[i], f0 + 0);
                    mma8(acc0[i][jp * 2 + 1], af[i], f0 + 2);
                    mma8(acc1[i][jp * 2 + 0], af[i], f1 + 0);
                    mma8(acc1[i][jp * 2 + 1], af[i], f1 + 2);
                }
            }
        }
    };

    loadA(0);  loadB(0);  storeA(0, 0); storeB(0, 0);
    loadA(32); loadB(32); storeA(0, 1); storeB(0, 1);
    __syncthreads();

    const int C = HID / 64;
    for (int c = 0; c < C; c++) {
        const int buf = c & 1;
        const bool more = (c + 1 < C);
        const int nk = (c + 1) * 64;
        if (more) { loadA(nk); loadB(nk); }
        compute(buf, 0);
        if (more) { storeA(buf ^ 1, 0); storeB(buf ^ 1, 0); loadA(nk + 32); loadB(nk + 32); }
        compute(buf, 1);
        if (more) { storeA(buf ^ 1, 1); storeB(buf ^ 1, 1); }
        __syncthreads();
    }

#pragma unroll
    for (int i = 0; i < 4; i++) {
#pragma unroll
        for (int h = 0; h < 2; h++) {
            int m = m0 + wm * 64 + i * 16 + gq + h * 8;
            if (m >= cnt) continue;
            int entry = g_pairs[e * NPAIRS + m];
            float* orow = g_inter + (size_t)entry * INTER + n0 + wn * 32;
#pragma unroll
            for (int j = 0; j < 4; j++) {
                float h0a = acc0[i][j][h * 2 + 0], h0b = acc0[i][j][h * 2 + 1];
                float h1a = acc1[i][j][h * 2 + 0], h1b = acc1[i][j][h * 2 + 1];
                float oa = tf(h0a / (1.0f + __expf(-h0a)) * h1a);
                float ob = tf(h0b / (1.0f + __expf(-h0b)) * h1b);
                *(float2*)(orow + j * 8 + tg * 2) = make_float2(oa, ob);
            }
        }
    }
}

// ---------------- GEMM2: inter @ wo[e], fused weighted combine -------------------
// Round-13 structure (best known). CTA 128M x 256N; warp tile 64x64;
// k-chunk 64 = 2 subtiles; double buffer; A via cp.async from tf32 g_inter.
__global__ __launch_bounds__(256, 1) void gemm2_mma(const float* __restrict__ wo,
                                                    float* __restrict__ out)
{
    const int e   = blockIdx.z;
    const int cnt = g_counts[e];
    const int m0  = blockIdx.y * 128;
    if (m0 >= cnt) return;
    const int n0  = blockIdx.x * 256;
    const float* Bg = wo + (size_t)e * INTER * HID;

    extern __shared__ float smf[];
    unsigned char* smc = (unsigned char*)smf;
    const uint32_t sb = smem_u32(smc);

    const int tid = threadIdx.x, lane = tid & 31, wid = tid >> 5;
    const int wm = wid >> 2, wn = wid & 3;
    const int gq = lane >> 2, tg = lane & 3;
    const int l7 = lane & 7;

    const uint32_t aLane = (uint32_t)(wm * 64 + l7 + ((lane >> 3) & 1) * 8) * 128u;
    const int      c4a   = lane >> 4;
    const uint32_t bLane = (uint32_t)(wn * 64 + ((lane >> 4) & 1) * 8 + l7) * 128u;
    const int      c4b   = (lane >> 3) & 1;

    const int row = tid >> 1, half = tid & 1;
    const float* arow;
    uint32_t asz;
    {
        int mg = m0 + row;
        if (mg < cnt) { arow = g_inter + (size_t)g_pairs[e * NPAIRS + mg] * INTER; asz = 16u; }
        else          { arow = g_inter; asz = 0u; }
    }
    auto cpA = [&](int buf, int k0, int sub) {
        const uint32_t st = sb + (uint32_t)buf * 32768u + (uint32_t)sub * 16384u;
#pragma unroll
        for (int q = 0; q < 4; q++) {
            int cchunk = half * 4 + q;
            uint32_t doff = (uint32_t)row * 128u + (uint32_t)((cchunk ^ (row & 7)) << 4);
            cpa_z(st + doff, arow + k0 + cchunk * 4, asz);
        }
    };

    const int bn = tid;
    float bR[32];
    auto loadB = [&](int k0) {
#pragma unroll
        for (int kk = 0; kk < 32; kk++)
            bR[kk] = Bg[(size_t)(k0 + kk) * HID + n0 + bn];
    };
    auto storeB = [&](int buf, int sub) {
        unsigned char* b = smc + 65536 + buf * 65536 + sub * 32768;
#pragma unroll
        for (int g = 0; g < 8; g++) {
            uint32_t byte = (uint32_t)bn * 128u + (uint32_t)((g ^ (bn & 7)) << 4);
            *(float4*)(b + byte) = make_float4(tf(bR[g*4]), tf(bR[g*4+1]), tf(bR[g*4+2]), tf(bR[g*4+3]));
        }
    };

    float acc[4][8][4] = {};

    auto compute = [&](int buf, int sub) {
        const uint32_t ab = sb + buf * 32768 + sub * 16384 + aLane;
        const uint32_t bb = sb + 65536 + buf * 65536 + sub * 32768 + bLane;
#pragma unroll
        for (int ks = 0; ks < 4; ks++) {
            const int kc = ks * 2;
            const uint32_t ca = (uint32_t)(((kc + c4a) ^ l7) << 4);
            const uint32_t cb = (uint32_t)(((kc + c4b) ^ l7) << 4);
            uint32_t af[4][4];
#pragma unroll
            for (int i = 0; i < 4; i++) ldsm4(af[i], ab + i * 2048 + ca);
#pragma unroll
            for (int jp = 0; jp < 4; jp++) {
                uint32_t bf[4];
                ldsm4(bf, bb + jp * 2048 + cb);
#pragma unroll
                for (int i = 0; i < 4; i++) {
                    mma8(acc[i][jp * 2 + 0], af[i], bf + 0);
                    mma8(acc[i][jp * 2 + 1], af[i], bf + 2);
                }
            }
        }
    };

    cpA(0, 0, 0); cpA(0, 32, 1); CP_COMMIT();
    loadB(0);  storeB(0, 0);
    loadB(32); storeB(0, 1);
    CP_WAIT0();
    __syncthreads();

    const int C = INTER / 64;
    for (int c = 0; c < C; c++) {
        const int buf = c & 1;
        const bool more = (c + 1 < C);
        const int nk = (c + 1) * 64;
        if (more) { cpA(buf ^ 1, nk, 0); cpA(buf ^ 1, nk + 32, 1); CP_COMMIT(); loadB(nk); }
        compute(buf, 0);
        if (more) { storeB(buf ^ 1, 0); loadB(nk + 32); }
        compute(buf, 1);
        if (more) storeB(buf ^ 1, 1);
        CP_WAIT0();
        __syncthreads();
    }

    // fused combine: out[token] += w * y  (bitwise deterministic)
#pragma unroll
    for (int i = 0; i < 4; i++) {
#pragma unroll
        for (int h = 0; h < 2; h++) {
            int m = m0 + wm * 64 + i * 16 + gq + h * 8;
            if (m >= cnt) continue;
            int entry = g_pairs[e * NPAIRS + m];
            float w = g_w[entry];
            float* base = out + (size_t)(entry >> 1) * HID + n0 + wn * 64 + tg * 2;
#pragma unroll
            for (int j = 0; j < 8; j++) {
                atomicAdd(base + j * 8 + 0, w * acc[i][j][h * 2 + 0]);
                atomicAdd(base + j * 8 + 1, w * acc[i][j][h * 2 + 1]);
            }
        }
    }
}

// ---------------- launch -------------------------------------------------------------
extern "C" void kernel_launch(void* const* d_in, const int* in_sizes, int n_in,
                              void* d_out, int out_size)
{
    const float* x      = (const float*)d_in[0];
    const float* logits = (const float*)d_in[1];
    const float* wi0    = (const float*)d_in[2];
    const float* wi1    = (const float*)d_in[3];
    const float* wo     = (const float*)d_in[4];
    float* out          = (float*)d_out;

    const int g1_smem = 196608;   // 192 KB
    const int g2_smem = 196608;   // 192 KB
    cudaFuncSetAttribute(gemm1_mma, cudaFuncAttributeMaxDynamicSharedMemorySize, g1_smem);
    cudaFuncSetAttribute(gemm2_mma, cudaFuncAttributeMaxDynamicSharedMemorySize, g2_smem);

    zero_out_kernel<<<(T_TOKENS * HID / 4) / 256, 256>>>(out);  // also zeroes g_counts
    route_kernel<<<T_TOKENS / 256, 256>>>(logits);

    dim3 g1(INTER / 128, NPAIRS / 128, NEXP);   // (16, 32, 8)
    gemm1_mma<<<g1, 256, g1_smem>>>(x, wi0, wi1);

    dim3 g2(HID / 256, NPAIRS / 128, NEXP);     // (4, 32, 8)
    gemm2_mma<<<g2, 256, g2_smem>>>(wo, out);
}